// round 4
// baseline (speedup 1.0000x reference)
#include <cuda_runtime.h>

#define BATCH 262144
#define DIM   128
#define K     10
#define TILE_ROWS 128
#define THREADS1  128
#define NBLK1     512
#define TILES_PER_BLK (BATCH / TILE_ROWS / NBLK1)   // 4

// Per-block column-sum partials (fully overwritten each replay; no init needed).
__device__ float g_part[NBLK1][K];

typedef unsigned long long u64;

__device__ __forceinline__ u64 pack2(float lo, float hi) {
    u64 r; asm("mov.b64 %0, {%1, %2};" : "=l"(r) : "f"(lo), "f"(hi)); return r;
}
__device__ __forceinline__ void unpack2(u64 v, float& lo, float& hi) {
    asm("mov.b64 {%0, %1}, %2;" : "=f"(lo), "=f"(hi) : "l"(v));
}
__device__ __forceinline__ void fma2(u64& acc, u64 a, u64 b) {
    asm("fma.rn.f32x2 %0, %1, %2, %0;" : "+l"(acc) : "l"(a), "l"(b));
}
__device__ __forceinline__ void cp_async16(unsigned smem_addr, const void* g) {
    asm volatile("cp.async.ca.shared.global [%0], [%1], 16;"
                 :: "r"(smem_addr), "l"(g) : "memory");
}

// Kernel 1: q = rownorm( 1/(1 + ||z-mu||^2) ) + per-block column partials.
// 128 threads (4 warps -> all 4 SMSPs). z staged tile-wise via cp.async into
// XOR-swizzled smem; each thread then owns one row -> register dots, no shuffles.
__global__ __launch_bounds__(THREADS1) void k_q(
    const float* __restrict__ z,
    const float* __restrict__ c,
    float* __restrict__ qout)
{
    __shared__ float4 s_z[TILE_ROWS * 32];  // 64 KB, XOR-swizzled rows
    __shared__ float4 s_c[K][32];           // centers, 5120 B
    __shared__ float  s_cn[K];              // ||c_j||^2
    __shared__ float  s_part[4][K];

    const int tid  = threadIdx.x;
    const int lane = tid & 31;
    const int wrp  = tid >> 5;

    for (int i = tid; i < K * 32; i += THREADS1)
        ((float4*)s_c)[i] = ((const float4*)c)[i];
    __syncthreads();
    if (tid < K) {
        float s = 0.0f;
        #pragma unroll
        for (int d = 0; d < 32; d++) {
            float4 v = s_c[tid][d];
            s = fmaf(v.x, v.x, fmaf(v.y, v.y, fmaf(v.z, v.z, fmaf(v.w, v.w, s))));
        }
        s_cn[tid] = s;   // visible after the first staging barrier
    }

    float csum[K];
    #pragma unroll
    for (int j = 0; j < K; j++) csum[j] = 0.0f;

    const int r  = tid;          // this thread's row within every tile
    const int r7 = r & 7;
    const unsigned s_z_base = (unsigned)__cvta_generic_to_shared(s_z);

    for (int t = 0; t < TILES_PER_BLK; t++) {
        const int tile = blockIdx.x * TILES_PER_BLK + t;
        const float4* zg = (const float4*)z + (size_t)tile * TILE_ROWS * 32;

        // Stage 64KB tile: warp-consecutive 16B chunks -> fully coalesced.
        #pragma unroll
        for (int k2 = 0; k2 < 32; k2++) {
            const int g   = k2 * THREADS1 + tid;   // [0, 4096)
            const int row = g >> 5;
            const int i   = g & 31;
            cp_async16(s_z_base + (unsigned)(row * 32 + (i ^ (row & 7))) * 16,
                       zg + g);
        }
        asm volatile("cp.async.commit_group;" ::: "memory");
        asm volatile("cp.async.wait_group 0;" ::: "memory");
        __syncthreads();

        u64 dot[K];
        #pragma unroll
        for (int j = 0; j < K; j++) dot[j] = 0ull;
        u64 zn = 0ull;

        #pragma unroll 8
        for (int i = 0; i < 32; i++) {
            float4 a = s_z[r * 32 + (i ^ r7)];
            u64 a01 = pack2(a.x, a.y), a23 = pack2(a.z, a.w);
            fma2(zn, a01, a01); fma2(zn, a23, a23);
            #pragma unroll
            for (int j = 0; j < K; j++) {
                float4 cc = s_c[j][i];               // broadcast LDS
                u64 c01 = pack2(cc.x, cc.y), c23 = pack2(cc.z, cc.w);
                fma2(dot[j], a01, c01); fma2(dot[j], a23, c23);
            }
        }

        float lo, hi;
        unpack2(zn, lo, hi);
        const float zz1 = 1.0f + (lo + hi);          // 1 + ||z||^2

        float q[K], rsum = 0.0f;
        #pragma unroll
        for (int j = 0; j < K; j++) {
            unpack2(dot[j], lo, hi);
            const float d = lo + hi;
            const float v = __fdividef(1.0f, fmaf(-2.0f, d, zz1 + s_cn[j]));
            q[j] = v; rsum += v;
        }
        const float inv = __fdividef(1.0f, rsum);

        const int row = tile * TILE_ROWS + r;
        float* orow = qout + (size_t)row * K;
        #pragma unroll
        for (int j = 0; j < K; j++) q[j] *= inv;
        #pragma unroll
        for (int m = 0; m < 5; m++) {
            float2 v; v.x = q[2 * m]; v.y = q[2 * m + 1];
            *(float2*)(orow + 2 * m) = v;
        }
        #pragma unroll
        for (int j = 0; j < K; j++) csum[j] += q[j];

        __syncthreads();   // protect s_z before next tile's staging
    }

    // One block-level reduction at the very end.
    #pragma unroll
    for (int j = 0; j < K; j++) {
        float v = csum[j];
        #pragma unroll
        for (int m = 16; m > 0; m >>= 1) v += __shfl_xor_sync(0xFFFFFFFFu, v, m);
        if (lane == 0) s_part[wrp][j] = v;
    }
    __syncthreads();
    if (tid < K)
        g_part[blockIdx.x][tid] =
            s_part[0][tid] + s_part[1][tid] + s_part[2][tid] + s_part[3][tid];
}

// Kernel 2: colsum finalize (each of 512 threads reads exactly one partial row),
// then p = rownorm(q^2 / colsum), 2 rows per thread.
__global__ __launch_bounds__(512) void k_p(
    const float* __restrict__ q,
    float* __restrict__ p)
{
    __shared__ float s_w[16][K];
    __shared__ float s_invf[K];

    const int tid  = threadIdx.x;
    const int lane = tid & 31;
    const int wrp  = tid >> 5;

    #pragma unroll
    for (int j = 0; j < K; j++) {
        float v = g_part[tid][j];
        #pragma unroll
        for (int m = 16; m > 0; m >>= 1) v += __shfl_xor_sync(0xFFFFFFFFu, v, m);
        if (lane == 0) s_w[wrp][j] = v;
    }
    __syncthreads();
    if (tid < K) {
        float s = 0.0f;
        #pragma unroll
        for (int w = 0; w < 16; w++) s += s_w[w][tid];
        s_invf[tid] = __fdividef(1.0f, s);
    }
    __syncthreads();

    float invf[K];
    #pragma unroll
    for (int j = 0; j < K; j++) invf[j] = s_invf[j];

    const int row0 = blockIdx.x * 1024 + tid;

    #pragma unroll
    for (int rr = 0; rr < 2; rr++) {
        const int row = row0 + rr * 512;
        const float2* qr = (const float2*)(q + (size_t)row * K);
        float2* pr = (float2*)(p + (size_t)row * K);

        float w[K], s = 0.0f;
        #pragma unroll
        for (int m = 0; m < K / 2; m++) {
            float2 v = qr[m];
            float w0 = v.x * v.x * invf[2 * m];
            float w1 = v.y * v.y * invf[2 * m + 1];
            w[2 * m] = w0; w[2 * m + 1] = w1;
            s += w0 + w1;
        }
        const float inv = __fdividef(1.0f, s);
        #pragma unroll
        for (int m = 0; m < K / 2; m++) {
            float2 v;
            v.x = w[2 * m] * inv;
            v.y = w[2 * m + 1] * inv;
            pr[m] = v;
        }
    }
}

extern "C" void kernel_launch(void* const* d_in, const int* in_sizes, int n_in,
                              void* d_out, int out_size) {
    const float* z = (const float*)d_in[0];
    const float* c = (const float*)d_in[1];
    float* qout = (float*)d_out;
    float* pout = (float*)d_out + (size_t)BATCH * K;

    k_q<<<NBLK1, THREADS1>>>(z, c, qout);
    k_p<<<BATCH / 1024, 512>>>(qout, pout);
}